// round 9
// baseline (speedup 1.0000x reference)
#include <cuda_runtime.h>

// Problem constants
static constexpr int Tt = 4;
static constexpr int Bb = 16;
static constexpr int Cc = 512;
static constexpr int Nn = 1024;
static constexpr int Cr = 64;
static constexpr int TB = Tt * Bb;     // 64 rows
static constexpr int BC = Bb * Cc;     // 8192 channels
static constexpr int NTASK = BC / 2;   // 4096 two-channel tasks

// Scratch (allocation-free: __device__ globals)
__device__ float g_buf[TB * Cc];       // GAP output [64, 512] row-major [r][c]
__device__ float h1nT_buf[Cr * TB];    // bn1 output TRANSPOSED [j][r]
// Monotonic grid-barrier state (2 syncs per launch, nb arrivals each ->
// counter is a multiple of nb at every launch start; barrier id
// B = ceil(v/nb) is launch-count independent). Proven in R3.
__device__ unsigned g_arrive;
__device__ volatile unsigned g_release;

// Scaled-LIF step (exact): u_t = v_t * 2^t. u += x*2^t; spike iff u >= 2^(t+1);
// hard reset u = 0. Power-of-2 scaling is exact in fp32 -> bitwise identical.
#define ULIF(u, xv, CT, TH, cnt) \
    do { u = fmaf((xv), (CT), u); if (u >= (TH)) { cnt += 1.0f; u = 0.0f; } } while (0)

__global__ void __launch_bounds__(256)
fused_kernel(const float* __restrict__ x,
             const float* __restrict__ w1, const float* __restrict__ b1,
             const float* __restrict__ gamma1, const float* __restrict__ beta1,
             const float* __restrict__ w2, const float* __restrict__ b2,
             const float* __restrict__ gamma2, const float* __restrict__ beta2,
             float* __restrict__ out, int nb)
{
    const int tid  = threadIdx.x;
    const int lane = tid & 31;
    const int warp = tid >> 5;

    __shared__ float sdata[8][8];            // phase A reduction
    __shared__ float ws[Cc];                 // phase B: w1 row
    __shared__ float h1s[TB];                // phase B: column values
    __shared__ float stats[2];               // phase B: mu, scale
    __shared__ float hT[Cr * (TB + 1)];      // phase C: h1nT padded [j*65+r]
    __shared__ float w2s[Cr];                // phase C: w2 row
    __shared__ float wsum[4];                // phase C: warp partials

    auto grid_sync = [&]() {
        __threadfence();
        __syncthreads();
        if (tid == 0) {
            unsigned v = atomicAdd(&g_arrive, 1u) + 1u;
            unsigned B = (v + (unsigned)nb - 1u) / (unsigned)nb;
            if (v == B * (unsigned)nb) g_release = B;
            while (g_release < B) { __nanosleep(32); }
            __threadfence();
        }
        __syncthreads();
    };

    // =====================================================================
    // Phase A: LIF multistep + GAP. Grid-stride over 4096 two-channel tasks;
    // per task the R2 block shape: 256 threads, 8 front-batched LDG.128.
    // =====================================================================
    {
        const float4* __restrict__ xp = reinterpret_cast<const float4*>(x);

        for (int task = blockIdx.x; task < NTASK; task += nb) {
            const int bc0 = task * 2;
            const int bc1 = bc0 + 1;

            float4 xa[Tt], xb[Tt];
            #pragma unroll
            for (int t = 0; t < Tt; t++) {
                xa[t] = xp[(size_t)(t * BC + bc0) * 256 + tid];
                xb[t] = xp[(size_t)(t * BC + bc1) * 256 + tid];
            }

            float ua0=0.f, ua1=0.f, ua2=0.f, ua3=0.f;
            float ub0=0.f, ub1=0.f, ub2=0.f, ub3=0.f;
            float c8[8];

            #pragma unroll
            for (int t = 0; t < Tt; t++) {
                const float CT = (float)(1 << t);        // 2^t
                const float TH = (float)(2 << t);        // 2^(t+1)
                float ca = 0.f, cb = 0.f;
                ULIF(ua0, xa[t].x, CT, TH, ca);
                ULIF(ua1, xa[t].y, CT, TH, ca);
                ULIF(ua2, xa[t].z, CT, TH, ca);
                ULIF(ua3, xa[t].w, CT, TH, ca);
                ULIF(ub0, xb[t].x, CT, TH, cb);
                ULIF(ub1, xb[t].y, CT, TH, cb);
                ULIF(ub2, xb[t].z, CT, TH, cb);
                ULIF(ub3, xb[t].w, CT, TH, cb);
                c8[t]     = ca;
                c8[t + 4] = cb;
            }

            #pragma unroll
            for (int k = 0; k < 8; k++) {
                float val = c8[k];
                #pragma unroll
                for (int off = 16; off > 0; off >>= 1)
                    val += __shfl_down_sync(0xffffffffu, val, off);
                if (lane == 0) sdata[warp][k] = val;
            }
            __syncthreads();

            if (tid < 8) {
                float s = 0.f;
                #pragma unroll
                for (int w = 0; w < 8; w++) s += sdata[w][tid];
                const int t  = tid & 3;
                const int bc = (tid < 4) ? bc0 : bc1;
                g_buf[t * BC + bc] = s * (1.0f / (float)Nn);
            }
            __syncthreads();
        }
    }

    grid_sync();

    // =====================================================================
    // Phase B: mm1 + bn1. Blocks 0..63 each own output column j; batched
    // loads (R7-proven body). Writes h1nT transposed.
    // =====================================================================
    if (blockIdx.x < Cr) {
        const int j = blockIdx.x;

        for (int i = tid; i < Cc; i += 256) ws[i] = w1[(size_t)j * Cc + i];
        __syncthreads();

        float acc[8];
        #pragma unroll
        for (int k = 0; k < 8; k++) acc[k] = 0.f;

        #pragma unroll
        for (int i = 0; i < 16; i++) {
            const int col = i * 32 + lane;
            const float wv = ws[col];
            #pragma unroll
            for (int k = 0; k < 8; k++)
                acc[k] += g_buf[(size_t)(warp * 8 + k) * Cc + col] * wv;
        }

        const float b1j = b1[j];
        #pragma unroll
        for (int k = 0; k < 8; k++) {
            float v = acc[k];
            #pragma unroll
            for (int off = 16; off > 0; off >>= 1)
                v += __shfl_down_sync(0xffffffffu, v, off);
            if (lane == 0) h1s[warp * 8 + k] = v + b1j;
        }
        __syncthreads();

        if (warp == 0) {
            float a = h1s[lane], b = h1s[lane + 32];
            float s  = a + b;
            float ss = a * a + b * b;
            #pragma unroll
            for (int off = 16; off > 0; off >>= 1) {
                s  += __shfl_down_sync(0xffffffffu, s,  off);
                ss += __shfl_down_sync(0xffffffffu, ss, off);
            }
            if (lane == 0) {
                float mu  = s * (1.0f / TB);
                float var = ss * (1.0f / TB) - mu * mu;
                if (var < 0.f) var = 0.f;
                stats[0] = mu;
                stats[1] = rsqrtf(var + 1e-5f) * gamma1[j];
            }
        }
        __syncthreads();

        if (tid < TB)
            h1nT_buf[j * TB + tid] = (h1s[tid] - stats[0]) * stats[1] + beta1[j];
    }

    grid_sync();

    // =====================================================================
    // Phase C: mm2 + bn2 + out. Block c owns output column c (grid-stride if
    // nb < 512). R8-proven body.
    // =====================================================================
    if (blockIdx.x < Cc) {
        // Stage h1nT: 4096 floats = 1024 float4, coalesced.
        {
            const float4* __restrict__ hp = reinterpret_cast<const float4*>(h1nT_buf);
            #pragma unroll
            for (int u = 0; u < 4; u++) {
                const int i4 = u * 256 + tid;
                float4 v = hp[i4];
                const int i  = i4 * 4;
                const int jj = i >> 6, rr = i & 63;
                float* d = &hT[jj * 65 + rr];
                d[0] = v.x; d[1] = v.y; d[2] = v.z; d[3] = v.w;
            }
        }

        for (int c = blockIdx.x; c < Cc; c += nb) {
            if (tid < Cr) w2s[tid] = w2[(size_t)c * Cr + tid];
            __syncthreads();

            float h = 0.f;
            if (tid < TB) {
                float acc = 0.f;
                #pragma unroll
                for (int j = 0; j < Cr; j++)
                    acc += hT[j * 65 + tid] * w2s[j];
                h = acc + b2[c];

                float s = h, ss = h * h;
                #pragma unroll
                for (int off = 16; off > 0; off >>= 1) {
                    s  += __shfl_down_sync(0xffffffffu, s,  off);
                    ss += __shfl_down_sync(0xffffffffu, ss, off);
                }
                if (lane == 0) { wsum[warp * 2] = s; wsum[warp * 2 + 1] = ss; }
            }
            __syncthreads();

            if (tid < TB) {
                const float S  = wsum[0] + wsum[2];
                const float SS = wsum[1] + wsum[3];
                const float mu = S * (1.0f / TB);
                float var = SS * (1.0f / TB) - mu * mu;
                if (var < 0.f) var = 0.f;
                const float sc = rsqrtf(var + 1e-5f) * gamma2[c];
                out[tid * Cc + c] = (h - mu) * sc + beta2[c];
            }
            __syncthreads();
        }
    }
}

// ---------------------------------------------------------------------------
extern "C" void kernel_launch(void* const* d_in, const int* in_sizes, int n_in,
                              void* d_out, int out_size) {
    const float* x      = (const float*)d_in[0];
    const float* w1     = (const float*)d_in[1];
    const float* b1     = (const float*)d_in[2];
    const float* gamma1 = (const float*)d_in[3];
    const float* beta1  = (const float*)d_in[4];
    const float* w2     = (const float*)d_in[5];
    const float* b2     = (const float*)d_in[6];
    const float* gamma2 = (const float*)d_in[7];
    const float* beta2  = (const float*)d_in[8];
    float* out = (float*)d_out;

    int dev = 0, sms = 0, maxb = 0;
    cudaGetDevice(&dev);
    cudaDeviceGetAttribute(&sms, cudaDevAttrMultiProcessorCount, dev);
    cudaOccupancyMaxActiveBlocksPerMultiprocessor(&maxb, fused_kernel, 256, 0);
    if (sms < 1) sms = 1;
    if (maxb < 1) maxb = 1;
    int nb = sms * maxb;
    if (nb > NTASK) nb = NTASK;

    fused_kernel<<<nb, 256>>>(x, w1, b1, gamma1, beta1,
                              w2, b2, gamma2, beta2, out, nb);
}

// round 10
// speedup vs baseline: 1.0937x; 1.0937x over previous
#include <cuda_runtime.h>

// Problem constants
static constexpr int Tt = 4;
static constexpr int Bb = 16;
static constexpr int Cc = 512;
static constexpr int Nn = 1024;
static constexpr int Cr = 64;
static constexpr int TB = Tt * Bb;     // 64 rows
static constexpr int BC = Bb * Cc;     // 8192 channels
static constexpr int NTASK = BC / 2;   // 4096 two-channel tasks
static constexpr int MAX_SLOTS = 32;   // supports nb >= 128 resident blocks

// Scratch (allocation-free: __device__ globals)
__device__ float g_buf[TB * Cc];       // GAP output [64, 512] row-major [r][c]
__device__ float h1nT_buf[Cr * TB];    // bn1 output TRANSPOSED [j][r]
// Monotonic grid-barrier state (2 syncs per launch, nb arrivals each ->
// counter is a multiple of nb at every launch start; barrier id
// B = ceil(v/nb) is launch-count independent). Proven R3/R9.
__device__ unsigned g_arrive;
__device__ volatile unsigned g_release;

// Scaled-LIF step (exact, bit-identical to reference; verified rel_err=0):
// u_t = v_t * 2^(t+1); u += x*2^t; spike iff u >= 2^(t+1); hard reset u = 0.
// Spike count packed into byte field t of pk (max 4/lane/field, 128/warp).
#define ULIF(u, xv, CT, TH, pk, INC) \
    do { u = fmaf((xv), (CT), u); if (u >= (TH)) { pk += (INC); u = 0.0f; } } while (0)

__global__ void __launch_bounds__(256)
fused_kernel(const float* __restrict__ x,
             const float* __restrict__ w1, const float* __restrict__ b1,
             const float* __restrict__ gamma1, const float* __restrict__ beta1,
             const float* __restrict__ w2, const float* __restrict__ b2,
             const float* __restrict__ gamma2, const float* __restrict__ beta2,
             float* __restrict__ out, int nb)
{
    const int tid  = threadIdx.x;
    const int lane = tid & 31;
    const int warp = tid >> 5;

    __shared__ unsigned sdataA[MAX_SLOTS][8][2];  // phase A: per-slot packed counts
    __shared__ float ws[Cc];                      // phase B: w1 row
    __shared__ float h1s[TB];                     // phase B: column values
    __shared__ float stats[2];                    // phase B: mu, scale
    __shared__ float hT[Cr * (TB + 1)];           // phase C: h1nT padded [j*65+r]
    __shared__ float w2s[Cr];                     // phase C: w2 row
    __shared__ float wsum[4];                     // phase C: warp partials

    auto grid_sync = [&]() {
        __threadfence();
        __syncthreads();
        if (tid == 0) {
            unsigned v = atomicAdd(&g_arrive, 1u) + 1u;
            unsigned B = (v + (unsigned)nb - 1u) / (unsigned)nb;
            if (v == B * (unsigned)nb) g_release = B;
            while (g_release < B) { __nanosleep(32); }
            __threadfence();
        }
        __syncthreads();
    };

    // =====================================================================
    // Phase A: LIF multistep + GAP. Grid-stride over 4096 two-channel tasks.
    // NO per-task __syncthreads: warp partials park in per-slot smem; one
    // sync after the loop, then all slots' g_buf writes.
    // =====================================================================
    {
        const float4* __restrict__ xp = reinterpret_cast<const float4*>(x);
        int nslots = 0;

        for (int task = blockIdx.x; task < NTASK; task += nb) {
            const int bc0 = task * 2;
            const int bc1 = bc0 + 1;

            float4 xa[Tt], xb[Tt];
            #pragma unroll
            for (int t = 0; t < Tt; t++) {
                xa[t] = xp[(size_t)(t * BC + bc0) * 256 + tid];
                xb[t] = xp[(size_t)(t * BC + bc1) * 256 + tid];
            }

            float ua0=0.f, ua1=0.f, ua2=0.f, ua3=0.f;
            float ub0=0.f, ub1=0.f, ub2=0.f, ub3=0.f;
            unsigned pa = 0u, pb = 0u;

            #pragma unroll
            for (int t = 0; t < Tt; t++) {
                const float    CT  = (float)(1 << t);   // 2^t
                const float    TH  = (float)(2 << t);   // 2^(t+1)
                const unsigned INC = 1u << (8 * t);
                ULIF(ua0, xa[t].x, CT, TH, pa, INC);
                ULIF(ua1, xa[t].y, CT, TH, pa, INC);
                ULIF(ua2, xa[t].z, CT, TH, pa, INC);
                ULIF(ua3, xa[t].w, CT, TH, pa, INC);
                ULIF(ub0, xb[t].x, CT, TH, pb, INC);
                ULIF(ub1, xb[t].y, CT, TH, pb, INC);
                ULIF(ub2, xb[t].z, CT, TH, pb, INC);
                ULIF(ub3, xb[t].w, CT, TH, pb, INC);
            }

            pa = __reduce_add_sync(0xffffffffu, pa);
            pb = __reduce_add_sync(0xffffffffu, pb);
            if (lane == 0) {
                sdataA[nslots][warp][0] = pa;
                sdataA[nslots][warp][1] = pb;
            }
            nslots++;
        }

        __syncthreads();   // the ONLY phase-A block barrier

        for (int sl = 0; sl < nslots; sl++) {
            if (tid < 8) {
                const int ch = tid >> 2;    // 0 or 1
                const int t  = tid & 3;
                unsigned s = 0;
                #pragma unroll
                for (int w = 0; w < 8; w++)
                    s += (sdataA[sl][w][ch] >> (8 * t)) & 0xFFu;
                const int task = blockIdx.x + sl * nb;
                g_buf[t * BC + task * 2 + ch] = (float)s * (1.0f / (float)Nn);
            }
        }
    }

    grid_sync();

    // =====================================================================
    // Phase B: mm1 + bn1. Blocks 0..63 own output column j (R9 body).
    // =====================================================================
    if (blockIdx.x < Cr) {
        const int j = blockIdx.x;

        for (int i = tid; i < Cc; i += 256) ws[i] = w1[(size_t)j * Cc + i];
        __syncthreads();

        float acc[8];
        #pragma unroll
        for (int k = 0; k < 8; k++) acc[k] = 0.f;

        #pragma unroll
        for (int i = 0; i < 16; i++) {
            const int col = i * 32 + lane;
            const float wv = ws[col];
            #pragma unroll
            for (int k = 0; k < 8; k++)
                acc[k] += g_buf[(size_t)(warp * 8 + k) * Cc + col] * wv;
        }

        const float b1j = b1[j];
        #pragma unroll
        for (int k = 0; k < 8; k++) {
            float v = acc[k];
            #pragma unroll
            for (int off = 16; off > 0; off >>= 1)
                v += __shfl_down_sync(0xffffffffu, v, off);
            if (lane == 0) h1s[warp * 8 + k] = v + b1j;
        }
        __syncthreads();

        if (warp == 0) {
            float a = h1s[lane], b = h1s[lane + 32];
            float s  = a + b;
            float ss = a * a + b * b;
            #pragma unroll
            for (int off = 16; off > 0; off >>= 1) {
                s  += __shfl_down_sync(0xffffffffu, s,  off);
                ss += __shfl_down_sync(0xffffffffu, ss, off);
            }
            if (lane == 0) {
                float mu  = s * (1.0f / TB);
                float var = ss * (1.0f / TB) - mu * mu;
                if (var < 0.f) var = 0.f;
                stats[0] = mu;
                stats[1] = rsqrtf(var + 1e-5f) * gamma1[j];
            }
        }
        __syncthreads();

        if (tid < TB)
            h1nT_buf[j * TB + tid] = (h1s[tid] - stats[0]) * stats[1] + beta1[j];
    }

    grid_sync();

    // =====================================================================
    // Phase C: mm2 + bn2 + out. Block c owns output column c (R9 body).
    // =====================================================================
    if (blockIdx.x < Cc) {
        {
            const float4* __restrict__ hp = reinterpret_cast<const float4*>(h1nT_buf);
            #pragma unroll
            for (int u = 0; u < 4; u++) {
                const int i4 = u * 256 + tid;
                float4 v = hp[i4];
                const int i  = i4 * 4;
                const int jj = i >> 6, rr = i & 63;
                float* d = &hT[jj * 65 + rr];
                d[0] = v.x; d[1] = v.y; d[2] = v.z; d[3] = v.w;
            }
        }

        for (int c = blockIdx.x; c < Cc; c += nb) {
            if (tid < Cr) w2s[tid] = w2[(size_t)c * Cr + tid];
            __syncthreads();

            float h = 0.f;
            if (tid < TB) {
                float acc = 0.f;
                #pragma unroll
                for (int j = 0; j < Cr; j++)
                    acc += hT[j * 65 + tid] * w2s[j];
                h = acc + b2[c];

                float s = h, ss = h * h;
                #pragma unroll
                for (int off = 16; off > 0; off >>= 1) {
                    s  += __shfl_down_sync(0xffffffffu, s,  off);
                    ss += __shfl_down_sync(0xffffffffu, ss, off);
                }
                if (lane == 0) { wsum[warp * 2] = s; wsum[warp * 2 + 1] = ss; }
            }
            __syncthreads();

            if (tid < TB) {
                const float S  = wsum[0] + wsum[2];
                const float SS = wsum[1] + wsum[3];
                const float mu = S * (1.0f / TB);
                float var = SS * (1.0f / TB) - mu * mu;
                if (var < 0.f) var = 0.f;
                const float sc = rsqrtf(var + 1e-5f) * gamma2[c];
                out[tid * Cc + c] = (h - mu) * sc + beta2[c];
            }
            __syncthreads();
        }
    }
}

// ---------------------------------------------------------------------------
extern "C" void kernel_launch(void* const* d_in, const int* in_sizes, int n_in,
                              void* d_out, int out_size) {
    const float* x      = (const float*)d_in[0];
    const float* w1     = (const float*)d_in[1];
    const float* b1     = (const float*)d_in[2];
    const float* gamma1 = (const float*)d_in[3];
    const float* beta1  = (const float*)d_in[4];
    const float* w2     = (const float*)d_in[5];
    const float* b2     = (const float*)d_in[6];
    const float* gamma2 = (const float*)d_in[7];
    const float* beta2  = (const float*)d_in[8];
    float* out = (float*)d_out;

    int dev = 0, sms = 0, maxb = 0;
    cudaGetDevice(&dev);
    cudaDeviceGetAttribute(&sms, cudaDevAttrMultiProcessorCount, dev);
    cudaOccupancyMaxActiveBlocksPerMultiprocessor(&maxb, fused_kernel, 256, 0);
    if (sms < 1) sms = 1;
    if (maxb < 1) maxb = 1;
    int nb = sms * maxb;              // all resident (required for grid sync)
    if (nb > NTASK) nb = NTASK;       // MAX_SLOTS=32 covers nb >= 128

    fused_kernel<<<nb, 256>>>(x, w1, b1, gamma1, beta1,
                              w2, b2, gamma2, beta2, out, nb);
}

// round 12
// speedup vs baseline: 1.1656x; 1.0657x over previous
#include <cuda_runtime.h>

// Problem constants
static constexpr int Tt = 4;
static constexpr int Bb = 16;
static constexpr int Cc = 512;
static constexpr int Nn = 1024;
static constexpr int Cr = 64;
static constexpr int TB = Tt * Bb;     // 64 rows
static constexpr int BC = Bb * Cc;     // 8192 channels (= phase-A tasks)
static constexpr int MAX_SLOTS = 32;   // supports nb >= 256 resident blocks

// Scratch (allocation-free: __device__ globals)
__device__ float g_buf[TB * Cc];       // GAP output [64, 512] row-major [r][c]
__device__ float h1nT_buf[Cr * TB];    // bn1 output TRANSPOSED [j][r]
// Monotonic grid-barrier state (2 syncs per launch, nb arrivals each ->
// counter is a multiple of nb at every launch start; barrier id
// B = ceil(v/nb) is launch-count independent). Proven R3/R9/R10.
__device__ unsigned g_arrive;
__device__ volatile unsigned g_release;

// Scaled-LIF step (exact, bit-identical; verified rel_err=0 in R9/R10):
// u_t = v_t * 2^t; u += x*2^t; spike iff u >= 2^(t+1); hard reset u = 0.
#define ULIF(u, xv, CT, TH, pk, INC) \
    do { u = fmaf((xv), (CT), u); if (u >= (TH)) { pk += (INC); u = 0.0f; } } while (0)

__global__ void __launch_bounds__(256)
fused_kernel(const float* __restrict__ x,
             const float* __restrict__ w1, const float* __restrict__ b1,
             const float* __restrict__ gamma1, const float* __restrict__ beta1,
             const float* __restrict__ w2, const float* __restrict__ b2,
             const float* __restrict__ gamma2, const float* __restrict__ beta2,
             float* __restrict__ out, int nb)
{
    const int tid  = threadIdx.x;
    const int lane = tid & 31;
    const int warp = tid >> 5;

    __shared__ unsigned sdataA[MAX_SLOTS][8];  // phase A: per-slot packed counts
    __shared__ float ws[Cc];                   // phase B: w1 row
    __shared__ float h1s[TB];                  // phase B: column values
    __shared__ float stats[2];                 // phase B: mu, scale
    __shared__ float hT[Cr * (TB + 1)];        // phase C: h1nT padded [j*65+r]
    __shared__ float w2s[Cr];                  // phase C: w2 row
    __shared__ float wsum[4];                  // phase C: warp partials

    auto grid_sync = [&]() {
        __threadfence();
        __syncthreads();
        if (tid == 0) {
            unsigned v = atomicAdd(&g_arrive, 1u) + 1u;
            unsigned B = (v + (unsigned)nb - 1u) / (unsigned)nb;
            if (v == B * (unsigned)nb) g_release = B;
            while (g_release < B) { __nanosleep(32); }
            __threadfence();
        }
        __syncthreads();
    };

    // =====================================================================
    // Phase A: LIF multistep + GAP. One CHANNEL per task (4 loads/thread),
    // software-pipelined: next task's loads issue BEFORE the current task's
    // reduce, so each warp always has loads in flight across the REDUX.
    // =====================================================================
    {
        const float4* __restrict__ xp = reinterpret_cast<const float4*>(x);
        int nslots = 0;
        int task = blockIdx.x;

        float4 cur0, cur1, cur2, cur3;
        if (task < BC) {
            cur0 = xp[(size_t)(0 * BC + task) * 256 + tid];
            cur1 = xp[(size_t)(1 * BC + task) * 256 + tid];
            cur2 = xp[(size_t)(2 * BC + task) * 256 + tid];
            cur3 = xp[(size_t)(3 * BC + task) * 256 + tid];
        }

        while (task < BC) {
            const int nxt_task = task + nb;
            float4 nxt0, nxt1, nxt2, nxt3;
            if (nxt_task < BC) {
                // Prefetch BEFORE the convergence op below.
                nxt0 = xp[(size_t)(0 * BC + nxt_task) * 256 + tid];
                nxt1 = xp[(size_t)(1 * BC + nxt_task) * 256 + tid];
                nxt2 = xp[(size_t)(2 * BC + nxt_task) * 256 + tid];
                nxt3 = xp[(size_t)(3 * BC + nxt_task) * 256 + tid];
            }

            float u0 = 0.f, u1 = 0.f, u2 = 0.f, u3 = 0.f;
            unsigned p = 0u;
            // t = 0
            ULIF(u0, cur0.x, 1.f, 2.f, p, 1u);
            ULIF(u1, cur0.y, 1.f, 2.f, p, 1u);
            ULIF(u2, cur0.z, 1.f, 2.f, p, 1u);
            ULIF(u3, cur0.w, 1.f, 2.f, p, 1u);
            // t = 1
            ULIF(u0, cur1.x, 2.f, 4.f, p, 1u << 8);
            ULIF(u1, cur1.y, 2.f, 4.f, p, 1u << 8);
            ULIF(u2, cur1.z, 2.f, 4.f, p, 1u << 8);
            ULIF(u3, cur1.w, 2.f, 4.f, p, 1u << 8);
            // t = 2
            ULIF(u0, cur2.x, 4.f, 8.f, p, 1u << 16);
            ULIF(u1, cur2.y, 4.f, 8.f, p, 1u << 16);
            ULIF(u2, cur2.z, 4.f, 8.f, p, 1u << 16);
            ULIF(u3, cur2.w, 4.f, 8.f, p, 1u << 16);
            // t = 3
            ULIF(u0, cur3.x, 8.f, 16.f, p, 1u << 24);
            ULIF(u1, cur3.y, 8.f, 16.f, p, 1u << 24);
            ULIF(u2, cur3.z, 8.f, 16.f, p, 1u << 24);
            ULIF(u3, cur3.w, 8.f, 16.f, p, 1u << 24);

            p = __reduce_add_sync(0xffffffffu, p);
            if (lane == 0) sdataA[nslots][warp] = p;
            nslots++;

            cur0 = nxt0; cur1 = nxt1; cur2 = nxt2; cur3 = nxt3;
            task = nxt_task;
        }

        __syncthreads();   // the ONLY phase-A block barrier

        for (int sl = 0; sl < nslots; sl++) {
            if (tid < 4) {
                unsigned s = 0;
                #pragma unroll
                for (int w = 0; w < 8; w++)
                    s += (sdataA[sl][w] >> (8 * tid)) & 0xFFu;
                const int tk = blockIdx.x + sl * nb;
                g_buf[tid * BC + tk] = (float)s * (1.0f / (float)Nn);
            }
        }
    }

    grid_sync();

    // =====================================================================
    // Phase B: mm1 + bn1. Blocks 0..63 own output column j (R9/R10 body).
    // =====================================================================
    if (blockIdx.x < Cr) {
        const int j = blockIdx.x;

        for (int i = tid; i < Cc; i += 256) ws[i] = w1[(size_t)j * Cc + i];
        __syncthreads();

        float acc[8];
        #pragma unroll
        for (int k = 0; k < 8; k++) acc[k] = 0.f;

        #pragma unroll
        for (int i = 0; i < 16; i++) {
            const int col = i * 32 + lane;
            const float wv = ws[col];
            #pragma unroll
            for (int k = 0; k < 8; k++)
                acc[k] += g_buf[(size_t)(warp * 8 + k) * Cc + col] * wv;
        }

        const float b1j = b1[j];
        #pragma unroll
        for (int k = 0; k < 8; k++) {
            float v = acc[k];
            #pragma unroll
            for (int off = 16; off > 0; off >>= 1)
                v += __shfl_down_sync(0xffffffffu, v, off);
            if (lane == 0) h1s[warp * 8 + k] = v + b1j;
        }
        __syncthreads();

        if (warp == 0) {
            float a = h1s[lane], b = h1s[lane + 32];
            float s  = a + b;
            float ss = a * a + b * b;
            #pragma unroll
            for (int off = 16; off > 0; off >>= 1) {
                s  += __shfl_down_sync(0xffffffffu, s,  off);
                ss += __shfl_down_sync(0xffffffffu, ss, off);
            }
            if (lane == 0) {
                float mu  = s * (1.0f / TB);
                float var = ss * (1.0f / TB) - mu * mu;
                if (var < 0.f) var = 0.f;
                stats[0] = mu;
                stats[1] = rsqrtf(var + 1e-5f) * gamma1[j];
            }
        }
        __syncthreads();

        if (tid < TB)
            h1nT_buf[j * TB + tid] = (h1s[tid] - stats[0]) * stats[1] + beta1[j];
    }

    grid_sync();

    // =====================================================================
    // Phase C: mm2 + bn2 + out. Block c owns output column c (R9/R10 body).
    // =====================================================================
    if (blockIdx.x < Cc) {
        {
            const float4* __restrict__ hp = reinterpret_cast<const float4*>(h1nT_buf);
            #pragma unroll
            for (int u = 0; u < 4; u++) {
                const int i4 = u * 256 + tid;
                float4 v = hp[i4];
                const int i  = i4 * 4;
                const int jj = i >> 6, rr = i & 63;
                float* d = &hT[jj * 65 + rr];
                d[0] = v.x; d[1] = v.y; d[2] = v.z; d[3] = v.w;
            }
        }

        for (int c = blockIdx.x; c < Cc; c += nb) {
            if (tid < Cr) w2s[tid] = w2[(size_t)c * Cr + tid];
            __syncthreads();

            float h = 0.f;
            if (tid < TB) {
                float acc = 0.f;
                #pragma unroll
                for (int j = 0; j < Cr; j++)
                    acc += hT[j * 65 + tid] * w2s[j];
                h = acc + b2[c];

                float s = h, ss = h * h;
                #pragma unroll
                for (int off = 16; off > 0; off >>= 1) {
                    s  += __shfl_down_sync(0xffffffffu, s,  off);
                    ss += __shfl_down_sync(0xffffffffu, ss, off);
                }
                if (lane == 0) { wsum[warp * 2] = s; wsum[warp * 2 + 1] = ss; }
            }
            __syncthreads();

            if (tid < TB) {
                const float S  = wsum[0] + wsum[2];
                const float SS = wsum[1] + wsum[3];
                const float mu = S * (1.0f / TB);
                float var = SS * (1.0f / TB) - mu * mu;
                if (var < 0.f) var = 0.f;
                const float sc = rsqrtf(var + 1e-5f) * gamma2[c];
                out[tid * Cc + c] = (h - mu) * sc + beta2[c];
            }
            __syncthreads();
        }
    }
}

// ---------------------------------------------------------------------------
extern "C" void kernel_launch(void* const* d_in, const int* in_sizes, int n_in,
                              void* d_out, int out_size) {
    const float* x      = (const float*)d_in[0];
    const float* w1     = (const float*)d_in[1];
    const float* b1     = (const float*)d_in[2];
    const float* gamma1 = (const float*)d_in[3];
    const float* beta1  = (const float*)d_in[4];
    const float* w2     = (const float*)d_in[5];
    const float* b2     = (const float*)d_in[6];
    const float* gamma2 = (const float*)d_in[7];
    const float* beta2  = (const float*)d_in[8];
    float* out = (float*)d_out;

    int dev = 0, sms = 0, maxb = 0;
    cudaGetDevice(&dev);
    cudaDeviceGetAttribute(&sms, cudaDevAttrMultiProcessorCount, dev);
    cudaOccupancyMaxActiveBlocksPerMultiprocessor(&maxb, fused_kernel, 256, 0);
    if (sms < 1) sms = 1;
    if (maxb < 1) maxb = 1;
    int nb = sms * maxb;              // all resident (required for grid sync)
    if (nb > BC) nb = BC;             // MAX_SLOTS=32 covers nb >= 256

    fused_kernel<<<nb, 256>>>(x, w1, b1, gamma1, beta1,
                              w2, b2, gamma2, beta2, out, nb);
}